// round 8
// baseline (speedup 1.0000x reference)
#include <cuda_runtime.h>
#include <cuda_fp16.h>
#include <cstdint>

#define EPS 1e-5f

__device__ __half g_Wh[384 * 256];
__device__ float g_bnsc[384];
__device__ float g_bnsh[384];

// smem byte offsets (K-chunk = 16)
#define OFF_A    0u        // A fp16: 3 bufs x 128 rows x 32B (swzA) = 12 KB
#define OFF_B16X 12288u    // B fp16 x: 2 bufs x 16 rows x 256B     = 8 KB
#define OFF_B16C 20480u    // B fp16 c: 2 bufs x 16 rows x 256B     = 8 KB
#define OFF_STGX 28672u    // staging fp32 x: 3 bufs x 16 x 512B    = 24 KB
#define OFF_STGC 53248u    // staging fp32 c: 3 bufs                = 24 KB
#define SMEM_TOTAL 77824   // 76 KB -> 2 CTAs/SM

// 32B-row swizzle (A tiles): bit4 ^= bit7
__device__ __forceinline__ uint32_t swzA(uint32_t o) { return o ^ ((o >> 3) & 0x10); }
// 256B-row swizzle (B tiles)
__device__ __forceinline__ uint32_t swzB(uint32_t o) { return o ^ ((o >> 4) & 0x70); }

__device__ __forceinline__ uint32_t s2u(const void* p) {
    uint32_t a;
    asm("{ .reg .u64 t; cvta.to.shared.u64 t, %1; cvt.u32.u64 %0, t; }" : "=r"(a) : "l"(p));
    return a;
}
__device__ __forceinline__ void ldsm_x4(uint32_t* r, uint32_t a) {
    asm volatile("ldmatrix.sync.aligned.m8n8.x4.shared.b16 {%0,%1,%2,%3}, [%4];"
                 : "=r"(r[0]), "=r"(r[1]), "=r"(r[2]), "=r"(r[3]) : "r"(a));
}
__device__ __forceinline__ void ldsm_x4t(uint32_t* r, uint32_t a) {
    asm volatile("ldmatrix.sync.aligned.m8n8.x4.trans.shared.b16 {%0,%1,%2,%3}, [%4];"
                 : "=r"(r[0]), "=r"(r[1]), "=r"(r[2]), "=r"(r[3]) : "r"(a));
}
__device__ __forceinline__ void mma16816(float* d, const uint32_t* a, const uint32_t* b) {
    asm volatile("mma.sync.aligned.m16n8k16.row.col.f32.f16.f16.f32 "
                 "{%0,%1,%2,%3}, {%4,%5,%6,%7}, {%8,%9}, {%0,%1,%2,%3};"
                 : "+f"(d[0]), "+f"(d[1]), "+f"(d[2]), "+f"(d[3])
                 : "r"(a[0]), "r"(a[1]), "r"(a[2]), "r"(a[3]), "r"(b[0]), "r"(b[1]));
}
__device__ __forceinline__ void cpa16(uint32_t dst, const void* src) {
    asm volatile("cp.async.cg.shared.global [%0], [%1], 16;" :: "r"(dst), "l"(src));
}

// ---------------- prep: W fp32 -> fp16, fold BN ----------------
__global__ void prep_kernel(const float* __restrict__ Wq, const float* __restrict__ Wv,
                            const float* __restrict__ Wk,
                            const float* __restrict__ qg, const float* __restrict__ qb,
                            const float* __restrict__ qm, const float* __restrict__ qv,
                            const float* __restrict__ vg, const float* __restrict__ vb,
                            const float* __restrict__ vm, const float* __restrict__ vv)
{
    int idx = blockIdx.x * blockDim.x + threadIdx.x;
    int stride = gridDim.x * blockDim.x;
    for (int i = idx; i < 384 * 256; i += stride) {
        int r = i >> 8, k = i & 255;
        float w = (r < 64) ? Wq[(r << 8) | k]
                : (r < 320) ? Wv[((r - 64) << 8) | k]
                            : Wk[((r - 320) << 8) | k];
        g_Wh[i] = __float2half_rn(w);
    }
    if (idx < 384) {
        float sc = 1.f, sh = 0.f;
        if (idx < 320) {
            float g, b, m, v;
            if (idx < 64) { g = qg[idx]; b = qb[idx]; m = qm[idx]; v = qv[idx]; }
            else { g = vg[idx-64]; b = vb[idx-64]; m = vm[idx-64]; v = vv[idx-64]; }
            sc = g * rsqrtf(v + EPS);
            sh = b - m * sc;
        }
        g_bnsc[idx] = sc; g_bnsh[idx] = sh;
    }
}

// ---------------- main: lookahead-pipelined fp16 HMMA GEMM ----------------
__global__ __launch_bounds__(256, 2)
void main_kernel(const float* __restrict__ x, const float* __restrict__ c,
                 float* __restrict__ out)
{
    extern __shared__ char smem[];
    const uint32_t sb = s2u(smem);
    const int tid = threadIdx.x, wid = tid >> 5, lane = tid & 31;
    const int mw = wid >> 1, nw = wid & 1;           // warp grid 4(M) x 2(N)
    const int bid = blockIdx.x;
    const int mblk = bid % 3;                        // ch blocks 0-127 / 128-255 / 256-383
    const int tile = bid / 3;
    const int b = tile >> 5, pxb = (tile & 31) << 7;
    const int ch0 = mblk << 7;

    float d[2][8][4];
    #pragma unroll
    for (int mt = 0; mt < 2; mt++)
        #pragma unroll
        for (int nt = 0; nt < 8; nt++)
            d[mt][nt][0] = d[mt][nt][1] = d[mt][nt][2] = d[mt][nt][3] = 0.f;

    const bool needX = (mblk == 0);
    // q channels (block0, mw<2) reduce over x; everything else over c
    const uint32_t offB = (mblk == 0 && mw < 2) ? OFF_B16X : OFF_B16C;

    // ---- async issue of chunk k (k16): A fp16 (buf k%3) + fp32 staging (buf k%3) ----
    auto issue = [&](int k) {
        const int kc = k << 4;
        const uint32_t asel = (uint32_t)(k % 3) * 4096u;
        const uint32_t ssel = (uint32_t)(k % 3) * 8192u;
        {   // A: 256 granules of 16B, one per thread
            int r = tid >> 1, u = tid & 1;
            cpa16(sb + OFF_A + asel + swzA((uint32_t)((r << 5) + (u << 4))),
                  g_Wh + ((ch0 + r) << 8) + kc + (u << 3));
        }
        #pragma unroll
        for (int i = 0; i < 2; i++) {                // staging c: 512 granules
            int idx = tid + (i << 8);
            int kk = idx >> 5, p = idx & 31;
            cpa16(sb + OFF_STGC + ssel + (uint32_t)((kk << 9) + (p << 4)),
                  c + (size_t)((b << 8) + kc + kk) * 4096 + pxb + (p << 2));
        }
        if (needX) {
            #pragma unroll
            for (int i = 0; i < 2; i++) {
                int idx = tid + (i << 8);
                int kk = idx >> 5, p = idx & 31;
                cpa16(sb + OFF_STGX + ssel + (uint32_t)((kk << 9) + (p << 4)),
                      x + (size_t)((b << 8) + kc + kk) * 4096 + pxb + (p << 2));
            }
        }
        asm volatile("cp.async.commit_group;");
    };

    // ---- per-thread convert of chunk k (reads only granules this thread wrote) ----
    auto convert = [&](int k) {
        const uint32_t ssel = (uint32_t)(k % 3) * 8192u;
        const uint32_t bsel = (uint32_t)(k & 1) * 4096u;
        #pragma unroll
        for (int i = 0; i < 2; i++) {
            int idx = tid + (i << 8);
            int kk = idx >> 5, p = idx & 31;
            float4 v = *(const float4*)(smem + OFF_STGC + ssel + (kk << 9) + (p << 4));
            __half2 h0 = __floats2half2_rn(v.x, v.y);
            __half2 h1 = __floats2half2_rn(v.z, v.w);
            *(uint2*)(smem + OFF_B16C + bsel + swzB((uint32_t)((kk << 8) + (p << 3)))) =
                make_uint2(*(uint32_t*)&h0, *(uint32_t*)&h1);
        }
        if (needX) {
            #pragma unroll
            for (int i = 0; i < 2; i++) {
                int idx = tid + (i << 8);
                int kk = idx >> 5, p = idx & 31;
                float4 v = *(const float4*)(smem + OFF_STGX + ssel + (kk << 9) + (p << 4));
                __half2 h0 = __floats2half2_rn(v.x, v.y);
                __half2 h1 = __floats2half2_rn(v.z, v.w);
                *(uint2*)(smem + OFF_B16X + bsel + swzB((uint32_t)((kk << 8) + (p << 3)))) =
                    make_uint2(*(uint32_t*)&h0, *(uint32_t*)&h1);
            }
        }
    };

    // prologue: two chunks in flight, convert chunk 0
    issue(0); issue(1);
    asm volatile("cp.async.wait_group 1;");
    convert(0);

    for (int ck = 0; ck < 16; ck++) {
        __syncthreads();                     // B16[ck] + A16[ck] published to all
        if (ck + 2 < 16) issue(ck + 2);
        if (ck + 1 < 16) {
            if (ck + 2 < 16) { asm volatile("cp.async.wait_group 1;"); }
            else             { asm volatile("cp.async.wait_group 0;"); }
            convert(ck + 1);                 // overlaps other warps' compute(ck)
        }

        const uint32_t abuf = sb + OFF_A + (uint32_t)(ck % 3) * 4096u;
        const uint32_t bbuf = sb + offB + (uint32_t)(ck & 1) * 4096u;
        uint32_t a[2][4], bf[8][2];
        #pragma unroll
        for (int mt = 0; mt < 2; mt++) {
            int row = (mw << 5) + (mt << 4) + (lane & 15);
            int kb  = (lane >> 4) << 4;
            ldsm_x4(a[mt], abuf + swzA((uint32_t)((row << 5) + kb)));
        }
        #pragma unroll
        for (int p = 0; p < 4; p++) {
            int krow = lane & 15;
            int ncol = (nw << 6) + (p << 4) + ((lane >> 4) << 3);
            uint32_t r[4];
            ldsm_x4t(r, bbuf + swzB((uint32_t)((krow << 8) + (ncol << 1))));
            bf[2*p][0] = r[0]; bf[2*p][1] = r[1];
            bf[2*p+1][0] = r[2]; bf[2*p+1][1] = r[3];
        }
        #pragma unroll
        for (int mt = 0; mt < 2; mt++)
            #pragma unroll
            for (int nt = 0; nt < 8; nt++)
                mma16816(d[mt][nt], a[mt], bf[nt]);
    }

    // ================= epilogue =================
    const int g = lane >> 2, cc = lane & 3;
    const bool isK = (mblk == 2 && mw >= 2);          // channels 320-383

    #pragma unroll
    for (int mt = 0; mt < 2; mt++) {
        const int chA = ch0 + (mw << 5) + (mt << 4) + g;
        float* oA = out + ((size_t)b * 384 + chA) * 4096 + pxb + (nw << 6);
        float* oB = oA + (size_t)8 * 4096;
        if (!isK) {
            float s0 = g_bnsc[chA],     h0 = g_bnsh[chA];
            float s1 = g_bnsc[chA + 8], h1 = g_bnsh[chA + 8];
            #pragma unroll
            for (int nt = 0; nt < 8; nt++) {
                int col = (nt << 3) + (cc << 1);
                *(float2*)(oA + col) = make_float2(fmaf(d[mt][nt][0], s0, h0),
                                                   fmaf(d[mt][nt][1], s0, h0));
                *(float2*)(oB + col) = make_float2(fmaf(d[mt][nt][2], s1, h1),
                                                   fmaf(d[mt][nt][3], s1, h1));
            }
        } else {
            // softmax over this warp's 64 cols = one full W row (4-thread quad per row)
            float mx0 = -3.4e38f, mx1 = -3.4e38f;
            #pragma unroll
            for (int nt = 0; nt < 8; nt++) {
                mx0 = fmaxf(mx0, fmaxf(d[mt][nt][0], d[mt][nt][1]));
                mx1 = fmaxf(mx1, fmaxf(d[mt][nt][2], d[mt][nt][3]));
            }
            mx0 = fmaxf(mx0, __shfl_xor_sync(0xffffffffu, mx0, 1));
            mx0 = fmaxf(mx0, __shfl_xor_sync(0xffffffffu, mx0, 2));
            mx1 = fmaxf(mx1, __shfl_xor_sync(0xffffffffu, mx1, 1));
            mx1 = fmaxf(mx1, __shfl_xor_sync(0xffffffffu, mx1, 2));
            float s0 = 0.f, s1 = 0.f;
            #pragma unroll
            for (int nt = 0; nt < 8; nt++) {
                d[mt][nt][0] = __expf(d[mt][nt][0] - mx0); s0 += d[mt][nt][0];
                d[mt][nt][1] = __expf(d[mt][nt][1] - mx0); s0 += d[mt][nt][1];
                d[mt][nt][2] = __expf(d[mt][nt][2] - mx1); s1 += d[mt][nt][2];
                d[mt][nt][3] = __expf(d[mt][nt][3] - mx1); s1 += d[mt][nt][3];
            }
            s0 += __shfl_xor_sync(0xffffffffu, s0, 1);
            s0 += __shfl_xor_sync(0xffffffffu, s0, 2);
            s1 += __shfl_xor_sync(0xffffffffu, s1, 1);
            s1 += __shfl_xor_sync(0xffffffffu, s1, 2);
            float i0 = __frcp_rn(s0), i1 = __frcp_rn(s1);
            #pragma unroll
            for (int nt = 0; nt < 8; nt++) {
                int col = (nt << 3) + (cc << 1);
                *(float2*)(oA + col) = make_float2(d[mt][nt][0] * i0, d[mt][nt][1] * i0);
                *(float2*)(oB + col) = make_float2(d[mt][nt][2] * i1, d[mt][nt][3] * i1);
            }
        }
    }
}

extern "C" void kernel_launch(void* const* d_in, const int* in_sizes, int n_in,
                              void* d_out, int out_size)
{
    const float* x = (const float*)d_in[0];
    const float* c = (const float*)d_in[1];
    prep_kernel<<<96, 256>>>((const float*)d_in[2], (const float*)d_in[3],
                             (const float*)d_in[4], (const float*)d_in[5],
                             (const float*)d_in[6], (const float*)d_in[7],
                             (const float*)d_in[8], (const float*)d_in[9],
                             (const float*)d_in[10], (const float*)d_in[11],
                             (const float*)d_in[12]);
    cudaFuncSetAttribute(main_kernel, cudaFuncAttributeMaxDynamicSharedMemorySize, SMEM_TOTAL);
    main_kernel<<<3072, 256, SMEM_TOTAL>>>(x, c, (float*)d_out);
}